// round 1
// baseline (speedup 1.0000x reference)
#include <cuda_runtime.h>
#include <cstddef>

// Problem constants
#define RR    64      // tie_attn_dim (MSA rows)
#define NN    512     // residues
#define DIMM  128     // d_msa
#define HH    8       // heads
#define DHH   64      // dim_head
#define INNERR 512    // HH*DHH
#define DPAIRR 128
#define DSW   16      // DIMM / HH

// ---------------- scratch (device globals; no allocation allowed) -------------
__device__ float g_q  [(size_t)RR * NN * INNERR];   // [r][n][h*64+d]
__device__ float g_k  [(size_t)RR * NN * INNERR];
__device__ float g_v  [(size_t)RR * NN * INNERR];
__device__ float g_sk [(size_t)RR * NN * DIMM];     // [r][n][c]
__device__ float g_sq [(size_t)NN * DIMM];          // [n][c]
__device__ float g_w  [(size_t)NN * HH * RR];       // [n][h][r]
__device__ float g_dots[(size_t)HH * NN * NN];      // [h][i][j]  (attn in-place)
__device__ float g_pb [(size_t)HH * NN * NN];       // [h][i][j]
__device__ float g_ctx[(size_t)RR * NN * INNERR];   // [r][i][h*64+d]

// ---------------- generic SGEMM: C = A(MxK) @ B(KxN) (+bias) -----------------
// BM=64, BN=64, BK=16, 256 threads, 4x4 micro-tile.
// grid = (N/64, M/64). All dims multiples of {64,64,16} here.
__global__ void sgemm_kernel(const float* __restrict__ A,
                             const float* __restrict__ B,
                             const float* __restrict__ bias,
                             float* __restrict__ C,
                             int K, int lda, int ldb, int ldc)
{
    __shared__ float As[16][64];
    __shared__ float Bs[16][64];
    const int tid = threadIdx.x;
    const int tx = tid & 15, ty = tid >> 4;
    const int row0 = blockIdx.y * 64, col0 = blockIdx.x * 64;

    const int m  = tid >> 2;         // 0..63
    const int kk = (tid & 3) * 4;    // 0,4,8,12
    const int kb = tid >> 4;         // 0..15
    const int nb = (tid & 15) * 4;   // 0..60

    float acc[4][4] = {};
    for (int k0 = 0; k0 < K; k0 += 16) {
        float4 a4 = *(const float4*)(A + (size_t)(row0 + m) * lda + k0 + kk);
        float4 b4 = *(const float4*)(B + (size_t)(k0 + kb) * ldb + col0 + nb);
        As[kk+0][m] = a4.x; As[kk+1][m] = a4.y; As[kk+2][m] = a4.z; As[kk+3][m] = a4.w;
        Bs[kb][nb+0] = b4.x; Bs[kb][nb+1] = b4.y; Bs[kb][nb+2] = b4.z; Bs[kb][nb+3] = b4.w;
        __syncthreads();
#pragma unroll
        for (int q2 = 0; q2 < 16; q2++) {
            float4 av = *(const float4*)&As[q2][ty * 4];
            float4 bv = *(const float4*)&Bs[q2][tx * 4];
            float a[4] = {av.x, av.y, av.z, av.w};
            float b[4] = {bv.x, bv.y, bv.z, bv.w};
#pragma unroll
            for (int i = 0; i < 4; i++)
#pragma unroll
                for (int j = 0; j < 4; j++) acc[i][j] += a[i] * b[j];
        }
        __syncthreads();
    }
#pragma unroll
    for (int i = 0; i < 4; i++) {
        int r = row0 + ty * 4 + i;
#pragma unroll
        for (int j = 0; j < 4; j++) {
            int c = col0 + tx * 4 + j;
            float vv = acc[i][j];
            if (bias) vv += bias[c];
            C[(size_t)r * ldc + c] = vv;
        }
    }
}

// ---------------- soft tied row weights: w[n][h][r] ---------------------------
// wlog[n,h,r] = dot(sq[n,h*16:..], sk[r,n,h*16:..]) / 4 ; softmax over r
__global__ void rowweight_kernel()
{
    const int n = blockIdx.x;   // 512
    const int h = blockIdx.y;   // 8
    const int r = threadIdx.x;  // 64
    __shared__ float sqv[16];
    __shared__ float buf[64];
    if (r < 16) sqv[r] = g_sq[(size_t)n * DIMM + h * DSW + r];
    __syncthreads();
    const float* skp = g_sk + ((size_t)r * NN + n) * DIMM + h * DSW;
    float dot = 0.f;
#pragma unroll
    for (int d = 0; d < 16; d++) dot += sqv[d] * skp[d];
    dot *= 0.25f;                 // 1/sqrt(16)
    buf[r] = dot;
    __syncthreads();
    float mx = buf[0];
#pragma unroll 8
    for (int t = 1; t < 64; t++) mx = fmaxf(mx, buf[t]);
    float e = expf(dot - mx);
    __syncthreads();
    buf[r] = e;
    __syncthreads();
    float s = 0.f;
#pragma unroll 8
    for (int t = 0; t < 64; t++) s += buf[t];
    g_w[(size_t)n * (HH * RR) + h * RR + r] = e / s;
}

// ---------------- pair bias: LN(pair[i,j,:]) @ Wpair -> g_pb[h][i][j] ---------
// One warp per (i,j) pair. 8 warps/block.
__global__ void pairbias_kernel(const float* __restrict__ pair,
                                const float* __restrict__ lng,
                                const float* __restrict__ lnb,
                                const float* __restrict__ Wp)
{
    const int lane = threadIdx.x & 31;
    const int warp = threadIdx.x >> 5;
    const size_t pidx = (size_t)blockIdx.x * 8 + warp;   // 0..262143
    const float* p = pair + pidx * DPAIRR;
    float4 xv = *(const float4*)(p + lane * 4);
    float s = xv.x + xv.y + xv.z + xv.w;
#pragma unroll
    for (int o = 16; o; o >>= 1) s += __shfl_xor_sync(0xffffffffu, s, o);
    const float mu = s * (1.f / 128.f);
    float d0 = xv.x - mu, d1 = xv.y - mu, d2 = xv.z - mu, d3 = xv.w - mu;
    float vs = d0 * d0 + d1 * d1 + d2 * d2 + d3 * d3;
#pragma unroll
    for (int o = 16; o; o >>= 1) vs += __shfl_xor_sync(0xffffffffu, vs, o);
    const float inv = rsqrtf(vs * (1.f / 128.f) + 1e-5f);
    const int c = lane * 4;
    float n0 = d0 * inv * lng[c + 0] + lnb[c + 0];
    float n1 = d1 * inv * lng[c + 1] + lnb[c + 1];
    float n2 = d2 * inv * lng[c + 2] + lnb[c + 2];
    float n3 = d3 * inv * lng[c + 3] + lnb[c + 3];
    float acc[8];
#pragma unroll
    for (int h = 0; h < 8; h++)
        acc[h] = n0 * Wp[(c + 0) * 8 + h] + n1 * Wp[(c + 1) * 8 + h]
               + n2 * Wp[(c + 2) * 8 + h] + n3 * Wp[(c + 3) * 8 + h];
#pragma unroll
    for (int h = 0; h < 8; h++)
#pragma unroll
        for (int o = 16; o; o >>= 1) acc[h] += __shfl_xor_sync(0xffffffffu, acc[h], o);
    if (lane < 8)
        g_pb[(size_t)lane * (NN * NN) + pidx] = acc[lane];
}

// ---------------- dots[h,i,j] = 0.125 * sum_r w[i,h,r] * (q_r[i]·k_r[j]) ------
// grid (8 jtiles, 8 itiles, 8 heads), 256 thr, 64x64 tile, 4x4 micro.
__global__ void dots_kernel()
{
    const int h  = blockIdx.z;
    const int i0 = blockIdx.y * 64;
    const int j0 = blockIdx.x * 64;
    const int tid = threadIdx.x;
    const int tx = tid & 15, ty = tid >> 4;
    __shared__ float Qs[16][64];
    __shared__ float Ks[16][64];
    __shared__ float Ws[64][64];   // [i_local][r]

    // preload per-i row weights for this head
#pragma unroll
    for (int l = 0; l < 16; l++) {
        int lin = tid + l * 256;          // 0..4095
        int ii = lin >> 6, rr = lin & 63;
        Ws[ii][rr] = g_w[(size_t)(i0 + ii) * (HH * RR) + h * RR + rr];
    }
    __syncthreads();

    const int m  = tid >> 2;
    const int kk = (tid & 3) * 4;
    float acc[4][4] = {};

    for (int r = 0; r < RR; r++) {
        const float* qb = g_q + (size_t)r * (NN * INNERR) + h * DHH;
        const float* kb = g_k + (size_t)r * (NN * INNERR) + h * DHH;
        float t[4][4] = {};
        for (int dd = 0; dd < 64; dd += 16) {
            float4 a4 = *(const float4*)(qb + (size_t)(i0 + m) * INNERR + dd + kk);
            float4 b4 = *(const float4*)(kb + (size_t)(j0 + m) * INNERR + dd + kk);
            Qs[kk+0][m] = a4.x; Qs[kk+1][m] = a4.y; Qs[kk+2][m] = a4.z; Qs[kk+3][m] = a4.w;
            Ks[kk+0][m] = b4.x; Ks[kk+1][m] = b4.y; Ks[kk+2][m] = b4.z; Ks[kk+3][m] = b4.w;
            __syncthreads();
#pragma unroll
            for (int q2 = 0; q2 < 16; q2++) {
                float4 av = *(const float4*)&Qs[q2][ty * 4];
                float4 bv = *(const float4*)&Ks[q2][tx * 4];
                float a[4] = {av.x, av.y, av.z, av.w};
                float b[4] = {bv.x, bv.y, bv.z, bv.w};
#pragma unroll
                for (int i = 0; i < 4; i++)
#pragma unroll
                    for (int j = 0; j < 4; j++) t[i][j] += a[i] * b[j];
            }
            __syncthreads();
        }
#pragma unroll
        for (int i = 0; i < 4; i++) {
            float wv = Ws[ty * 4 + i][r];
#pragma unroll
            for (int j = 0; j < 4; j++) acc[i][j] += wv * t[i][j];
        }
    }
#pragma unroll
    for (int i = 0; i < 4; i++)
#pragma unroll
        for (int j = 0; j < 4; j++)
            g_dots[((size_t)h * NN + i0 + ty * 4 + i) * NN + j0 + tx * 4 + j] =
                acc[i][j] * 0.125f;
}

// ---------------- softmax over j of (dots + pb), in-place in g_dots -----------
__global__ void softmax_kernel()
{
    const int i = blockIdx.x, h = blockIdx.y;
    float* row = g_dots + ((size_t)h * NN + i) * NN;
    const float* pb = g_pb + ((size_t)h * NN + i) * NN;
    const int t = threadIdx.x;  // 128
    __shared__ float red[128];
    float v[4];
    float mx = -1e30f;
#pragma unroll
    for (int e = 0; e < 4; e++) { v[e] = row[t * 4 + e] + pb[t * 4 + e]; mx = fmaxf(mx, v[e]); }
    red[t] = mx; __syncthreads();
#pragma unroll
    for (int s = 64; s; s >>= 1) { if (t < s) red[t] = fmaxf(red[t], red[t + s]); __syncthreads(); }
    const float M = red[0];
    __syncthreads();
    float sum = 0.f;
#pragma unroll
    for (int e = 0; e < 4; e++) { v[e] = expf(v[e] - M); sum += v[e]; }
    red[t] = sum; __syncthreads();
#pragma unroll
    for (int s = 64; s; s >>= 1) { if (t < s) red[t] += red[t + s]; __syncthreads(); }
    const float inv = 1.f / red[0];
#pragma unroll
    for (int e = 0; e < 4; e++) row[t * 4 + e] = v[e] * inv;
}

// ---------------- ctx[r,i,h*64+d] = sum_j attn[h,i,j] * v[r,j,h*64+d] ---------
// grid (8 itiles, 8 heads, 64 rows). 64x64 tile over (i,d), K=512 (j).
__global__ void ctx_kernel()
{
    const int i0 = blockIdx.x * 64;
    const int h  = blockIdx.y;
    const int r  = blockIdx.z;
    const float* A = g_dots + (size_t)h * (NN * NN);               // [i][j], ld 512
    const float* B = g_v + (size_t)r * (NN * INNERR) + h * DHH;    // [j][d], ld 512
    float* C = g_ctx + (size_t)r * (NN * INNERR) + h * DHH;        // [i][d], ld 512

    __shared__ float As[16][64];
    __shared__ float Bs[16][64];
    const int tid = threadIdx.x;
    const int tx = tid & 15, ty = tid >> 4;
    const int m  = tid >> 2;
    const int kk = (tid & 3) * 4;
    const int kb = tid >> 4;
    const int nb = (tid & 15) * 4;
    float acc[4][4] = {};

    for (int k0 = 0; k0 < NN; k0 += 16) {
        float4 a4 = *(const float4*)(A + (size_t)(i0 + m) * NN + k0 + kk);
        float4 b4 = *(const float4*)(B + (size_t)(k0 + kb) * INNERR + nb);
        As[kk+0][m] = a4.x; As[kk+1][m] = a4.y; As[kk+2][m] = a4.z; As[kk+3][m] = a4.w;
        Bs[kb][nb+0] = b4.x; Bs[kb][nb+1] = b4.y; Bs[kb][nb+2] = b4.z; Bs[kb][nb+3] = b4.w;
        __syncthreads();
#pragma unroll
        for (int q2 = 0; q2 < 16; q2++) {
            float4 av = *(const float4*)&As[q2][ty * 4];
            float4 bv = *(const float4*)&Bs[q2][tx * 4];
            float a[4] = {av.x, av.y, av.z, av.w};
            float b[4] = {bv.x, bv.y, bv.z, bv.w};
#pragma unroll
            for (int i = 0; i < 4; i++)
#pragma unroll
                for (int j = 0; j < 4; j++) acc[i][j] += a[i] * b[j];
        }
        __syncthreads();
    }
#pragma unroll
    for (int i = 0; i < 4; i++)
#pragma unroll
        for (int j = 0; j < 4; j++)
            C[(size_t)(i0 + ty * 4 + i) * INNERR + tx * 4 + j] = acc[i][j];
}

// ------------------------------ host ------------------------------------------
static float* symaddr(const void* s)
{
    void* p = nullptr;
    cudaGetSymbolAddress(&p, s);
    return (float*)p;
}

extern "C" void kernel_launch(void* const* d_in, const int* in_sizes, int n_in,
                              void* d_out, int out_size)
{
    const float* x     = (const float*)d_in[0];
    const float* pair  = (const float*)d_in[1];
    const float* Wq    = (const float*)d_in[2];
    const float* Wkv   = (const float*)d_in[3];
    const float* Wo    = (const float*)d_in[4];
    const float* bo    = (const float*)d_in[5];
    const float* lng   = (const float*)d_in[6];
    const float* lnb   = (const float*)d_in[7];
    const float* Wpair = (const float*)d_in[8];
    const float* Wsq   = (const float*)d_in[9];
    const float* bsq   = (const float*)d_in[10];
    const float* Wsk   = (const float*)d_in[11];
    const float* bsk   = (const float*)d_in[12];
    float* out = (float*)d_out;

    float* pq   = symaddr(g_q);
    float* pk   = symaddr(g_k);
    float* pv   = symaddr(g_v);
    float* psk  = symaddr(g_sk);
    float* psq  = symaddr(g_sq);
    float* pctx = symaddr(g_ctx);

    dim3 blk(256);

    // projections (M = R*N = 32768 rows of x, K = 128)
    sgemm_kernel<<<dim3(INNERR / 64, (RR * NN) / 64), blk>>>(x, Wq,        nullptr, pq,  DIMM, DIMM, INNERR,     INNERR);
    sgemm_kernel<<<dim3(INNERR / 64, (RR * NN) / 64), blk>>>(x, Wkv,       nullptr, pk,  DIMM, DIMM, 2 * INNERR, INNERR);
    sgemm_kernel<<<dim3(INNERR / 64, (RR * NN) / 64), blk>>>(x, Wkv + 512, nullptr, pv,  DIMM, DIMM, 2 * INNERR, INNERR);
    sgemm_kernel<<<dim3(DIMM / 64,   (RR * NN) / 64), blk>>>(x, Wsk,       bsk,     psk, DIMM, DIMM, DIMM,       DIMM);
    sgemm_kernel<<<dim3(DIMM / 64,   NN / 64),        blk>>>(x, Wsq,       bsq,     psq, DIMM, DIMM, DIMM,       DIMM);

    // soft tied row weights
    rowweight_kernel<<<dim3(NN, HH), 64>>>();

    // pair bias (memory-bound: 134 MB read)
    pairbias_kernel<<<(NN * NN) / 8, 256>>>(pair, lng, lnb, Wpair);

    // tied attention logits
    dots_kernel<<<dim3(8, 8, 8), blk>>>();

    // softmax over j (adds pair bias)
    softmax_kernel<<<dim3(NN, HH), 128>>>();

    // attn @ V
    ctx_kernel<<<dim3(8, HH, RR), blk>>>();

    // output projection: (32768 x 512) @ (512 x 128) + bo
    sgemm_kernel<<<dim3(DIMM / 64, (RR * NN) / 64), blk>>>(pctx, Wo, bo, out, INNERR, INNERR, DIMM, DIMM);
}

// round 3
// speedup vs baseline: 1.5433x; 1.5433x over previous
#include <cuda_runtime.h>
#include <cstddef>
#include <cstdint>

// Problem constants
#define RR    64      // tie_attn_dim (MSA rows)
#define NN    512     // residues
#define DIMM  128     // d_msa
#define HH    8       // heads
#define DHH   64      // dim_head
#define INNERR 512    // HH*DHH
#define DPAIRR 128
#define DSW   16      // DIMM / HH

// ---------------- scratch (device globals; no allocation allowed) -------------
__device__ float g_q  [(size_t)RR * NN * INNERR];   // [r][n][h*64+d]
__device__ float g_k  [(size_t)RR * NN * INNERR];
__device__ float g_v  [(size_t)RR * NN * INNERR];
__device__ float g_sk [(size_t)RR * NN * DIMM];     // [r][n][c]
__device__ float g_sq [(size_t)NN * DIMM];          // [n][c]
__device__ float g_w  [(size_t)NN * HH * RR];       // [n][h][r]  (pre-scaled by 0.125)
__device__ float g_dots[(size_t)HH * NN * NN];      // [h][i][j]  (attn in-place)
__device__ float g_pb [(size_t)HH * NN * NN];       // [h][i][j]
__device__ float g_ctx[(size_t)RR * NN * INNERR];   // [r][i][h*64+d]

// ---------------- tf32 helpers ------------------------------------------------
__device__ __forceinline__ unsigned f2tf(float f)
{
    unsigned u;
    asm("cvt.rna.tf32.f32 %0, %1;" : "=r"(u) : "f"(f));
    return u;
}

__device__ __forceinline__ void mma8(float* d, const unsigned* a, const unsigned* b)
{
    asm volatile(
        "mma.sync.aligned.m16n8k8.row.col.f32.tf32.tf32.f32 "
        "{%0,%1,%2,%3},{%4,%5,%6,%7},{%8,%9},{%0,%1,%2,%3};"
        : "+f"(d[0]), "+f"(d[1]), "+f"(d[2]), "+f"(d[3])
        : "r"(a[0]), "r"(a[1]), "r"(a[2]), "r"(a[3]), "r"(b[0]), "r"(b[1]));
}

// ---------------- generic TF32 GEMM: C = A(MxK) @ B(KxN) (+bias) --------------
// BM=128, BN=128, BK=16, 256 thr = 8 warps (2x4), warp tile 64x32.
// All dims multiples of tile sizes here. A row-major, B row-major.
__global__ void __launch_bounds__(256)
gemm_tf32_nn(const float* __restrict__ A, int lda,
             const float* __restrict__ B, int ldb,
             const float* __restrict__ bias,
             float* __restrict__ C, int ldc, int K)
{
    __shared__ unsigned As[128][20];   // [m][k], pad 4
    __shared__ unsigned Bs[16][136];   // [k][n], pad 8
    const int t = threadIdx.x;
    const int lane = t & 31, warp = t >> 5;
    const int i0 = blockIdx.y * 128, j0 = blockIdx.x * 128;
    const int wm = (warp >> 2) * 64, wn = (warp & 3) * 32;
    const int g = lane >> 2, c = lane & 3;

    const int ar = t >> 2;           // 0..63 (+64)
    const int ak = 4 * (t & 3);
    const int bk = t >> 5;           // 0..7 (+8)
    const int bn = 4 * (t & 31);

    float acc[4][4][4] = {};
    for (int k0 = 0; k0 < K; k0 += 16) {
        float4 a0 = *(const float4*)(A + (size_t)(i0 + ar) * lda + k0 + ak);
        float4 a1 = *(const float4*)(A + (size_t)(i0 + ar + 64) * lda + k0 + ak);
        float4 b0 = *(const float4*)(B + (size_t)(k0 + bk) * ldb + j0 + bn);
        float4 b1 = *(const float4*)(B + (size_t)(k0 + bk + 8) * ldb + j0 + bn);
        As[ar][ak + 0] = f2tf(a0.x); As[ar][ak + 1] = f2tf(a0.y);
        As[ar][ak + 2] = f2tf(a0.z); As[ar][ak + 3] = f2tf(a0.w);
        As[ar + 64][ak + 0] = f2tf(a1.x); As[ar + 64][ak + 1] = f2tf(a1.y);
        As[ar + 64][ak + 2] = f2tf(a1.z); As[ar + 64][ak + 3] = f2tf(a1.w);
        *(uint4*)&Bs[bk][bn]     = make_uint4(f2tf(b0.x), f2tf(b0.y), f2tf(b0.z), f2tf(b0.w));
        *(uint4*)&Bs[bk + 8][bn] = make_uint4(f2tf(b1.x), f2tf(b1.y), f2tf(b1.z), f2tf(b1.w));
        __syncthreads();
#pragma unroll
        for (int ks = 0; ks < 16; ks += 8) {
            unsigned af[4][4], bf[4][2];
#pragma unroll
            for (int mf = 0; mf < 4; mf++) {
                int r0 = wm + mf * 16;
                af[mf][0] = As[r0 + g][ks + c];
                af[mf][1] = As[r0 + g + 8][ks + c];
                af[mf][2] = As[r0 + g][ks + c + 4];
                af[mf][3] = As[r0 + g + 8][ks + c + 4];
            }
#pragma unroll
            for (int nf = 0; nf < 4; nf++) {
                int n = wn + nf * 8 + g;
                bf[nf][0] = Bs[ks + c][n];
                bf[nf][1] = Bs[ks + c + 4][n];
            }
#pragma unroll
            for (int mf = 0; mf < 4; mf++)
#pragma unroll
                for (int nf = 0; nf < 4; nf++) mma8(acc[mf][nf], af[mf], bf[nf]);
        }
        __syncthreads();
    }
#pragma unroll
    for (int mf = 0; mf < 4; mf++) {
        int row = i0 + wm + mf * 16 + g;
#pragma unroll
        for (int nf = 0; nf < 4; nf++) {
            int col = j0 + wn + nf * 8 + 2 * c;
            float bv0 = bias ? bias[col] : 0.f;
            float bv1 = bias ? bias[col + 1] : 0.f;
            float* p0 = C + (size_t)row * ldc + col;
            float* p1 = C + (size_t)(row + 8) * ldc + col;
            p0[0] = acc[mf][nf][0] + bv0; p0[1] = acc[mf][nf][1] + bv1;
            p1[0] = acc[mf][nf][2] + bv0; p1[1] = acc[mf][nf][3] + bv1;
        }
    }
}

// ---------------- soft tied row weights: w[n][h][r] (pre-scaled by 0.125) -----
__global__ void rowweight_kernel()
{
    const int n = blockIdx.x, h = blockIdx.y;
    const int r = threadIdx.x;  // 64
    __shared__ float sqv[16];
    __shared__ float buf[64];
    if (r < 16) sqv[r] = g_sq[(size_t)n * DIMM + h * DSW + r];
    __syncthreads();
    const float* skp = g_sk + ((size_t)r * NN + n) * DIMM + h * DSW;
    float dot = 0.f;
#pragma unroll
    for (int d = 0; d < 16; d++) dot += sqv[d] * skp[d];
    dot *= 0.25f;
    buf[r] = dot;
    __syncthreads();
    float mx = buf[0];
#pragma unroll 8
    for (int t2 = 1; t2 < 64; t2++) mx = fmaxf(mx, buf[t2]);
    float e = expf(dot - mx);
    __syncthreads();
    buf[r] = e;
    __syncthreads();
    float s = 0.f;
#pragma unroll 8
    for (int t2 = 0; t2 < 64; t2++) s += buf[t2];
    g_w[(size_t)n * (HH * RR) + h * RR + r] = (e / s) * 0.125f;  // fold dh^-0.5
}

// ---------------- pair bias: LN(pair[i,j,:]) @ Wpair -> g_pb[h][i][j] ---------
__global__ void pairbias_kernel(const float* __restrict__ pair,
                                const float* __restrict__ lng,
                                const float* __restrict__ lnb,
                                const float* __restrict__ Wp)
{
    const int lane = threadIdx.x & 31;
    const int warp = threadIdx.x >> 5;
    const size_t pidx = (size_t)blockIdx.x * 8 + warp;
    const float* p = pair + pidx * DPAIRR;
    float4 xv = *(const float4*)(p + lane * 4);
    float s = xv.x + xv.y + xv.z + xv.w;
#pragma unroll
    for (int o = 16; o; o >>= 1) s += __shfl_xor_sync(0xffffffffu, s, o);
    const float mu = s * (1.f / 128.f);
    float d0 = xv.x - mu, d1 = xv.y - mu, d2 = xv.z - mu, d3 = xv.w - mu;
    float vs = d0 * d0 + d1 * d1 + d2 * d2 + d3 * d3;
#pragma unroll
    for (int o = 16; o; o >>= 1) vs += __shfl_xor_sync(0xffffffffu, vs, o);
    const float inv = rsqrtf(vs * (1.f / 128.f) + 1e-5f);
    const int c = lane * 4;
    float n0 = d0 * inv * lng[c + 0] + lnb[c + 0];
    float n1 = d1 * inv * lng[c + 1] + lnb[c + 1];
    float n2 = d2 * inv * lng[c + 2] + lnb[c + 2];
    float n3 = d3 * inv * lng[c + 3] + lnb[c + 3];
    float acc[8];
#pragma unroll
    for (int h = 0; h < 8; h++)
        acc[h] = n0 * Wp[(c + 0) * 8 + h] + n1 * Wp[(c + 1) * 8 + h]
               + n2 * Wp[(c + 2) * 8 + h] + n3 * Wp[(c + 3) * 8 + h];
#pragma unroll
    for (int h = 0; h < 8; h++)
#pragma unroll
        for (int o = 16; o; o >>= 1) acc[h] += __shfl_xor_sync(0xffffffffu, acc[h], o);
    if (lane < 8)
        g_pb[(size_t)lane * (NN * NN) + pidx] = acc[lane];
}

// ---------------- dots: per-head NT GEMM with K = R*DH = 4096 ------------------
// dots[h,i,j] = sum_{r,d} (w[i,h,r]*q[r,i,h,d]) * k[r,j,h,d]  + pb[h,i,j]
// A[i,kk] = w*q (kk=r*64+d), B[j,kk] = k. Both K-major. Tiles 128x128x16.
__global__ void __launch_bounds__(256)
dots_tf32()
{
    const int h  = blockIdx.z;
    const int i0 = blockIdx.y * 128;
    const int j0 = blockIdx.x * 128;
    __shared__ unsigned As[128][20];
    __shared__ unsigned Bs[128][20];
    const int t = threadIdx.x;
    const int lane = t & 31, warp = t >> 5;
    const int wm = (warp >> 2) * 64, wn = (warp & 3) * 32;
    const int g = lane >> 2, c = lane & 3;
    const int ar = t >> 2;
    const int ak = 4 * (t & 3);

    float acc[4][4][4] = {};
    for (int k0 = 0; k0 < RR * DHH; k0 += 16) {
        const int r  = k0 >> 6;
        const int d0 = (k0 & 63) + ak;
        const float* qb = g_q + (size_t)r * (NN * INNERR) + h * DHH;
        const float* kb = g_k + (size_t)r * (NN * INNERR) + h * DHH;
        float wv0 = g_w[(size_t)(i0 + ar) * (HH * RR) + h * RR + r];
        float wv1 = g_w[(size_t)(i0 + ar + 64) * (HH * RR) + h * RR + r];
        float4 a0 = *(const float4*)(qb + (size_t)(i0 + ar) * INNERR + d0);
        float4 a1 = *(const float4*)(qb + (size_t)(i0 + ar + 64) * INNERR + d0);
        float4 b0 = *(const float4*)(kb + (size_t)(j0 + ar) * INNERR + d0);
        float4 b1 = *(const float4*)(kb + (size_t)(j0 + ar + 64) * INNERR + d0);
        As[ar][ak + 0] = f2tf(a0.x * wv0); As[ar][ak + 1] = f2tf(a0.y * wv0);
        As[ar][ak + 2] = f2tf(a0.z * wv0); As[ar][ak + 3] = f2tf(a0.w * wv0);
        As[ar + 64][ak + 0] = f2tf(a1.x * wv1); As[ar + 64][ak + 1] = f2tf(a1.y * wv1);
        As[ar + 64][ak + 2] = f2tf(a1.z * wv1); As[ar + 64][ak + 3] = f2tf(a1.w * wv1);
        Bs[ar][ak + 0] = f2tf(b0.x); Bs[ar][ak + 1] = f2tf(b0.y);
        Bs[ar][ak + 2] = f2tf(b0.z); Bs[ar][ak + 3] = f2tf(b0.w);
        Bs[ar + 64][ak + 0] = f2tf(b1.x); Bs[ar + 64][ak + 1] = f2tf(b1.y);
        Bs[ar + 64][ak + 2] = f2tf(b1.z); Bs[ar + 64][ak + 3] = f2tf(b1.w);
        __syncthreads();
#pragma unroll
        for (int ks = 0; ks < 16; ks += 8) {
            unsigned af[4][4], bf[4][2];
#pragma unroll
            for (int mf = 0; mf < 4; mf++) {
                int r0 = wm + mf * 16;
                af[mf][0] = As[r0 + g][ks + c];
                af[mf][1] = As[r0 + g + 8][ks + c];
                af[mf][2] = As[r0 + g][ks + c + 4];
                af[mf][3] = As[r0 + g + 8][ks + c + 4];
            }
#pragma unroll
            for (int nf = 0; nf < 4; nf++) {
                int n = wn + nf * 8 + g;
                bf[nf][0] = Bs[n][ks + c];
                bf[nf][1] = Bs[n][ks + c + 4];
            }
#pragma unroll
            for (int mf = 0; mf < 4; mf++)
#pragma unroll
                for (int nf = 0; nf < 4; nf++) mma8(acc[mf][nf], af[mf], bf[nf]);
        }
        __syncthreads();
    }
    // epilogue: + pair bias, store logits
    float* Cbase = g_dots + (size_t)h * (NN * NN);
    const float* Pbase = g_pb + (size_t)h * (NN * NN);
#pragma unroll
    for (int mf = 0; mf < 4; mf++) {
        int row = i0 + wm + mf * 16 + g;
#pragma unroll
        for (int nf = 0; nf < 4; nf++) {
            int col = j0 + wn + nf * 8 + 2 * c;
            float2 pb0 = *(const float2*)(Pbase + (size_t)row * NN + col);
            float2 pb1 = *(const float2*)(Pbase + (size_t)(row + 8) * NN + col);
            float2 o0 = make_float2(acc[mf][nf][0] + pb0.x, acc[mf][nf][1] + pb0.y);
            float2 o1 = make_float2(acc[mf][nf][2] + pb1.x, acc[mf][nf][3] + pb1.y);
            *(float2*)(Cbase + (size_t)row * NN + col) = o0;
            *(float2*)(Cbase + (size_t)(row + 8) * NN + col) = o1;
        }
    }
}

// ---------------- softmax over j of g_dots, in-place ---------------------------
__global__ void softmax_kernel()
{
    const int i = blockIdx.x, h = blockIdx.y;
    float* row = g_dots + ((size_t)h * NN + i) * NN;
    const int t = threadIdx.x;  // 128
    __shared__ float red[128];
    float v[4];
    float mx = -1e30f;
#pragma unroll
    for (int e = 0; e < 4; e++) { v[e] = row[t * 4 + e]; mx = fmaxf(mx, v[e]); }
    red[t] = mx; __syncthreads();
#pragma unroll
    for (int s = 64; s; s >>= 1) { if (t < s) red[t] = fmaxf(red[t], red[t + s]); __syncthreads(); }
    const float M = red[0];
    __syncthreads();
    float sum = 0.f;
#pragma unroll
    for (int e = 0; e < 4; e++) { v[e] = expf(v[e] - M); sum += v[e]; }
    red[t] = sum; __syncthreads();
#pragma unroll
    for (int s = 64; s; s >>= 1) { if (t < s) red[t] += red[t + s]; __syncthreads(); }
    const float inv = 1.f / red[0];
#pragma unroll
    for (int e = 0; e < 4; e++) row[t * 4 + e] = v[e] * inv;
}

// ---------------- ctx: per-head NN GEMM, N flattened over (r,d) = 4096 --------
// ctx[r,i,h*64+d] = sum_j attn[h,i,j] * v[r,j,h*64+d]
__global__ void __launch_bounds__(256)
ctx_tf32()
{
    const int h  = blockIdx.z;
    const int i0 = blockIdx.y * 128;
    const int n0 = blockIdx.x * 128;   // flattened (r,d) col tile
    __shared__ unsigned As[128][20];
    __shared__ unsigned Bs[16][136];
    const int t = threadIdx.x;
    const int lane = t & 31, warp = t >> 5;
    const int wm = (warp >> 2) * 64, wn = (warp & 3) * 32;
    const int g = lane >> 2, c = lane & 3;
    const int ar = t >> 2;
    const int ak = 4 * (t & 3);
    const int bk = t >> 5;
    const int bn = 4 * (t & 31);

    const float* A = g_dots + (size_t)h * (NN * NN);
    // B col addressing for this block's 128-col tile
    const int cg_b = n0 + bn;
    const float* Bp = g_v + (size_t)(cg_b >> 6) * (NN * INNERR) + h * DHH + (cg_b & 63);

    float acc[4][4][4] = {};
    for (int k0 = 0; k0 < NN; k0 += 16) {
        float4 a0 = *(const float4*)(A + (size_t)(i0 + ar) * NN + k0 + ak);
        float4 a1 = *(const float4*)(A + (size_t)(i0 + ar + 64) * NN + k0 + ak);
        float4 b0 = *(const float4*)(Bp + (size_t)(k0 + bk) * INNERR);
        float4 b1 = *(const float4*)(Bp + (size_t)(k0 + bk + 8) * INNERR);
        As[ar][ak + 0] = f2tf(a0.x); As[ar][ak + 1] = f2tf(a0.y);
        As[ar][ak + 2] = f2tf(a0.z); As[ar][ak + 3] = f2tf(a0.w);
        As[ar + 64][ak + 0] = f2tf(a1.x); As[ar + 64][ak + 1] = f2tf(a1.y);
        As[ar + 64][ak + 2] = f2tf(a1.z); As[ar + 64][ak + 3] = f2tf(a1.w);
        *(uint4*)&Bs[bk][bn]     = make_uint4(f2tf(b0.x), f2tf(b0.y), f2tf(b0.z), f2tf(b0.w));
        *(uint4*)&Bs[bk + 8][bn] = make_uint4(f2tf(b1.x), f2tf(b1.y), f2tf(b1.z), f2tf(b1.w));
        __syncthreads();
#pragma unroll
        for (int ks = 0; ks < 16; ks += 8) {
            unsigned af[4][4], bf[4][2];
#pragma unroll
            for (int mf = 0; mf < 4; mf++) {
                int r0 = wm + mf * 16;
                af[mf][0] = As[r0 + g][ks + c];
                af[mf][1] = As[r0 + g + 8][ks + c];
                af[mf][2] = As[r0 + g][ks + c + 4];
                af[mf][3] = As[r0 + g + 8][ks + c + 4];
            }
#pragma unroll
            for (int nf = 0; nf < 4; nf++) {
                int n = wn + nf * 8 + g;
                bf[nf][0] = Bs[ks + c][n];
                bf[nf][1] = Bs[ks + c + 4][n];
            }
#pragma unroll
            for (int mf = 0; mf < 4; mf++)
#pragma unroll
                for (int nf = 0; nf < 4; nf++) mma8(acc[mf][nf], af[mf], bf[nf]);
        }
        __syncthreads();
    }
#pragma unroll
    for (int mf = 0; mf < 4; mf++) {
        int row = i0 + wm + mf * 16 + g;
#pragma unroll
        for (int nf = 0; nf < 4; nf++) {
            int cg = n0 + wn + nf * 8 + 2 * c;
            float* p = g_ctx + (size_t)(cg >> 6) * (NN * INNERR) + h * DHH + (cg & 63);
            *(float2*)(p + (size_t)row * INNERR)       = make_float2(acc[mf][nf][0], acc[mf][nf][1]);
            *(float2*)(p + (size_t)(row + 8) * INNERR) = make_float2(acc[mf][nf][2], acc[mf][nf][3]);
        }
    }
}

// ------------------------------ host ------------------------------------------
static float* symaddr(const void* s)
{
    void* p = nullptr;
    cudaGetSymbolAddress(&p, s);
    return (float*)p;
}

extern "C" void kernel_launch(void* const* d_in, const int* in_sizes, int n_in,
                              void* d_out, int out_size)
{
    const float* x     = (const float*)d_in[0];
    const float* pair  = (const float*)d_in[1];
    const float* Wq    = (const float*)d_in[2];
    const float* Wkv   = (const float*)d_in[3];
    const float* Wo    = (const float*)d_in[4];
    const float* bo    = (const float*)d_in[5];
    const float* lng   = (const float*)d_in[6];
    const float* lnb   = (const float*)d_in[7];
    const float* Wpair = (const float*)d_in[8];
    const float* Wsq   = (const float*)d_in[9];
    const float* bsq   = (const float*)d_in[10];
    const float* Wsk   = (const float*)d_in[11];
    const float* bsk   = (const float*)d_in[12];
    float* out = (float*)d_out;

    float* pq   = symaddr(g_q);
    float* pk   = symaddr(g_k);
    float* pv   = symaddr(g_v);
    float* psk  = symaddr(g_sk);
    float* psq  = symaddr(g_sq);
    float* pctx = symaddr(g_ctx);

    dim3 blk(256);
    const int MROWS = RR * NN;   // 32768

    // projections (TF32 tensor cores)
    gemm_tf32_nn<<<dim3(INNERR / 128, MROWS / 128), blk>>>(x, DIMM, Wq,        INNERR,     nullptr, pq,  INNERR, DIMM);
    gemm_tf32_nn<<<dim3(INNERR / 128, MROWS / 128), blk>>>(x, DIMM, Wkv,       2 * INNERR, nullptr, pk,  INNERR, DIMM);
    gemm_tf32_nn<<<dim3(INNERR / 128, MROWS / 128), blk>>>(x, DIMM, Wkv + 512, 2 * INNERR, nullptr, pv,  INNERR, DIMM);
    gemm_tf32_nn<<<dim3(DIMM / 128,   MROWS / 128), blk>>>(x, DIMM, Wsk,       DIMM,       bsk,     psk, DIMM,   DIMM);
    gemm_tf32_nn<<<dim3(DIMM / 128,   NN / 128),    blk>>>(x, DIMM, Wsq,       DIMM,       bsq,     psq, DIMM,   DIMM);

    // soft tied row weights (x0.125 folded in)
    rowweight_kernel<<<dim3(NN, HH), 64>>>();

    // pair bias (memory-bound: 134 MB read)
    pairbias_kernel<<<(NN * NN) / 8, 256>>>(pair, lng, lnb, Wpair);

    // tied attention logits (+pair bias in epilogue)
    dots_tf32<<<dim3(4, 4, HH), blk>>>();

    // softmax over j
    softmax_kernel<<<dim3(NN, HH), 128>>>();

    // attn @ V
    ctx_tf32<<<dim3(32, 4, HH), blk>>>();

    // output projection
    gemm_tf32_nn<<<dim3(DIMM / 128, MROWS / 128), blk>>>(pctx, INNERR, Wo, DIMM, bo, out, DIMM, INNERR);
}

// round 4
// speedup vs baseline: 1.8155x; 1.1764x over previous
#include <cuda_runtime.h>
#include <cstddef>
#include <cstdint>

// Problem constants
#define RR    64      // tie_attn_dim (MSA rows)
#define NN    512     // residues
#define DIMM  128     // d_msa
#define HH    8       // heads
#define DHH   64      // dim_head
#define INNERR 512    // HH*DHH
#define DPAIRR 128
#define DSW   16      // DIMM / HH
#define KBIG  4096    // RR*DHH
#define HSZ   ((size_t)NN * KBIG)   // per-head packed size

// ---------------- scratch (device globals; no allocation allowed) -------------
__device__ float g_aq [(size_t)HH * NN * KBIG];   // [h][n][r*64+d] = w*q (tf32-rounded)
__device__ float g_ak [(size_t)HH * NN * KBIG];   // [h][n][r*64+d] = k   (tf32-rounded)
__device__ float g_vp [(size_t)HH * NN * KBIG];   // [h][j][r*64+d] = v   (tf32-rounded)
__device__ float g_sk [(size_t)RR * NN * DIMM];   // [r][n][c]
__device__ float g_sq [(size_t)NN * DIMM];        // [n][c]
__device__ float g_w  [(size_t)NN * HH * RR];     // [n][h][r]  (pre-scaled 0.125)
__device__ float g_dots[(size_t)HH * NN * NN];    // [h][i][j]  (attn in-place)
__device__ float g_pb [(size_t)HH * NN * NN];     // [h][i][j]
__device__ float g_ctx[(size_t)RR * NN * INNERR]; // [(r,i)][h*64+d]

// ---------------- helpers ------------------------------------------------------
__device__ __forceinline__ unsigned f2tf(float f)
{
    unsigned u;
    asm("cvt.rna.tf32.f32 %0, %1;" : "=r"(u) : "f"(f));
    return u;
}
__device__ __forceinline__ float f2tff(float f) { return __uint_as_float(f2tf(f)); }

__device__ __forceinline__ void mma8(float* d, const unsigned* a, const unsigned* b)
{
    asm volatile(
        "mma.sync.aligned.m16n8k8.row.col.f32.tf32.tf32.f32 "
        "{%0,%1,%2,%3},{%4,%5,%6,%7},{%8,%9},{%0,%1,%2,%3};"
        : "+f"(d[0]), "+f"(d[1]), "+f"(d[2]), "+f"(d[3])
        : "r"(a[0]), "r"(a[1]), "r"(a[2]), "r"(a[3]), "r"(b[0]), "r"(b[1]));
}

__device__ __forceinline__ void cp16(void* dst, const void* src)
{
    unsigned s = (unsigned)__cvta_generic_to_shared(dst);
    asm volatile("cp.async.cg.shared.global [%0], [%1], 16;\n" :: "r"(s), "l"(src));
}
__device__ __forceinline__ void cp_commit() { asm volatile("cp.async.commit_group;\n"); }
template<int W> __device__ __forceinline__ void cp_wait()
{
    asm volatile("cp.async.wait_group %0;\n" :: "n"(W));
}

// ---------------- generic NN TF32 GEMM with cp.async pipeline ------------------
// BM=128, BN=128, BK=16, 256 thr, warp tile 64x32.
// EPI=0: C[row*ldc+col] = acc (+bias)
// EPI=1: packed remap: col->ch=col>>6; base=(ch<8?C:C2)+(ch&7)*HSZ;
//        addr = n*4096 + r*64 + d   (n=row&511, r=row>>9, d=col&63), tf32-rounded
// EPI=2: like EPI=1 (C only), multiplied by wtab[n*512 + h*64 + r]
template<int EPI>
__global__ void __launch_bounds__(256)
gemm_nn(const float* __restrict__ A, int lda,
        const float* __restrict__ B, int ldb,
        const float* __restrict__ bias,
        float* __restrict__ C, int ldc,
        float* __restrict__ C2,
        const float* __restrict__ wtab,
        int K)
{
    __shared__ float As[2][128][20];
    __shared__ float Bs[2][16][136];
    const int t = threadIdx.x, lane = t & 31, warp = t >> 5;
    const int i0 = blockIdx.y * 128, j0 = blockIdx.x * 128;
    const int wm = (warp >> 2) * 64, wn = (warp & 3) * 32;
    const int g = lane >> 2, c = lane & 3;
    const int ar = t >> 2, ak = 4 * (t & 3);
    const int bk = t >> 5, bn = 4 * (t & 31);

    const float* Ab = A + (size_t)i0 * lda;
    const float* Bb = B + j0;

    auto stage = [&](int k0, int s) {
        cp16(&As[s][ar][ak],      Ab + (size_t)ar * lda + k0 + ak);
        cp16(&As[s][ar + 64][ak], Ab + (size_t)(ar + 64) * lda + k0 + ak);
        cp16(&Bs[s][bk][bn],      Bb + (size_t)(k0 + bk) * ldb + bn);
        cp16(&Bs[s][bk + 8][bn],  Bb + (size_t)(k0 + bk + 8) * ldb + bn);
    };

    float acc[4][4][4] = {};
    stage(0, 0); cp_commit();
    const int nit = K / 16;
    for (int it = 0; it < nit; ++it) {
        const int s = it & 1;
        if (it + 1 < nit) { stage((it + 1) * 16, s ^ 1); cp_commit(); cp_wait<1>(); }
        else cp_wait<0>();
        __syncthreads();
#pragma unroll
        for (int ks = 0; ks < 16; ks += 8) {
            unsigned af[4][4], bf[4][2];
#pragma unroll
            for (int mf = 0; mf < 4; mf++) {
                int r0 = wm + mf * 16;
                af[mf][0] = f2tf(As[s][r0 + g][ks + c]);
                af[mf][1] = f2tf(As[s][r0 + g + 8][ks + c]);
                af[mf][2] = f2tf(As[s][r0 + g][ks + c + 4]);
                af[mf][3] = f2tf(As[s][r0 + g + 8][ks + c + 4]);
            }
#pragma unroll
            for (int nf = 0; nf < 4; nf++) {
                int n = wn + nf * 8 + g;
                bf[nf][0] = f2tf(Bs[s][ks + c][n]);
                bf[nf][1] = f2tf(Bs[s][ks + c + 4][n]);
            }
#pragma unroll
            for (int mf = 0; mf < 4; mf++)
#pragma unroll
                for (int nf = 0; nf < 4; nf++) mma8(acc[mf][nf], af[mf], bf[nf]);
        }
        __syncthreads();
    }

#pragma unroll
    for (int mf = 0; mf < 4; mf++) {
        const int row0 = i0 + wm + mf * 16 + g;
#pragma unroll
        for (int nf = 0; nf < 4; nf++) {
            const int col = j0 + wn + nf * 8 + 2 * c;
            if (EPI == 0) {
                float b0 = bias ? bias[col] : 0.f;
                float b1 = bias ? bias[col + 1] : 0.f;
                *(float2*)(C + (size_t)row0 * ldc + col) =
                    make_float2(acc[mf][nf][0] + b0, acc[mf][nf][1] + b1);
                *(float2*)(C + (size_t)(row0 + 8) * ldc + col) =
                    make_float2(acc[mf][nf][2] + b0, acc[mf][nf][3] + b1);
            } else {
                const int ch = col >> 6, d = col & 63;
                float* base = ((EPI == 1 && ch >= 8) ? C2 : C) + (size_t)(ch & 7) * HSZ;
                const int n0r = row0 & 511, r0r = row0 >> 9;
                const int n1r = (row0 + 8) & 511, r1r = (row0 + 8) >> 9;
                float w0 = 1.f, w1 = 1.f;
                if (EPI == 2) {
                    w0 = wtab[(size_t)n0r * 512 + (ch << 6) + r0r];
                    w1 = wtab[(size_t)n1r * 512 + (ch << 6) + r1r];
                }
                *(float2*)(base + (size_t)n0r * KBIG + r0r * 64 + d) =
                    make_float2(f2tff(acc[mf][nf][0] * w0), f2tff(acc[mf][nf][1] * w0));
                *(float2*)(base + (size_t)n1r * KBIG + r1r * 64 + d) =
                    make_float2(f2tff(acc[mf][nf][2] * w1), f2tff(acc[mf][nf][3] * w1));
            }
        }
    }
}

// ---------------- dots: per-head NT GEMM, K=4096, + pair bias epilogue ---------
__global__ void __launch_bounds__(256)
dots_nt()
{
    const int h  = blockIdx.z;
    const int i0 = blockIdx.y * 128, j0 = blockIdx.x * 128;
    __shared__ float As[2][128][20];
    __shared__ float Bs[2][128][20];
    const int t = threadIdx.x, lane = t & 31, warp = t >> 5;
    const int wm = (warp >> 2) * 64, wn = (warp & 3) * 32;
    const int g = lane >> 2, c = lane & 3;
    const int ar = t >> 2, ak = 4 * (t & 3);

    const float* Ab = g_aq + (size_t)h * HSZ + (size_t)i0 * KBIG;
    const float* Bb = g_ak + (size_t)h * HSZ + (size_t)j0 * KBIG;

    auto stage = [&](int k0, int s) {
        cp16(&As[s][ar][ak],      Ab + (size_t)ar * KBIG + k0 + ak);
        cp16(&As[s][ar + 64][ak], Ab + (size_t)(ar + 64) * KBIG + k0 + ak);
        cp16(&Bs[s][ar][ak],      Bb + (size_t)ar * KBIG + k0 + ak);
        cp16(&Bs[s][ar + 64][ak], Bb + (size_t)(ar + 64) * KBIG + k0 + ak);
    };

    float acc[4][4][4] = {};
    stage(0, 0); cp_commit();
    const int nit = KBIG / 16;   // 256
    for (int it = 0; it < nit; ++it) {
        const int s = it & 1;
        if (it + 1 < nit) { stage((it + 1) * 16, s ^ 1); cp_commit(); cp_wait<1>(); }
        else cp_wait<0>();
        __syncthreads();
#pragma unroll
        for (int ks = 0; ks < 16; ks += 8) {
            unsigned af[4][4], bf[4][2];
#pragma unroll
            for (int mf = 0; mf < 4; mf++) {
                int r0 = wm + mf * 16;
                af[mf][0] = __float_as_uint(As[s][r0 + g][ks + c]);
                af[mf][1] = __float_as_uint(As[s][r0 + g + 8][ks + c]);
                af[mf][2] = __float_as_uint(As[s][r0 + g][ks + c + 4]);
                af[mf][3] = __float_as_uint(As[s][r0 + g + 8][ks + c + 4]);
            }
#pragma unroll
            for (int nf = 0; nf < 4; nf++) {
                int n = wn + nf * 8 + g;
                bf[nf][0] = __float_as_uint(Bs[s][n][ks + c]);
                bf[nf][1] = __float_as_uint(Bs[s][n][ks + c + 4]);
            }
#pragma unroll
            for (int mf = 0; mf < 4; mf++)
#pragma unroll
                for (int nf = 0; nf < 4; nf++) mma8(acc[mf][nf], af[mf], bf[nf]);
        }
        __syncthreads();
    }

    float* Cb = g_dots + (size_t)h * (NN * NN);
    const float* Pb = g_pb + (size_t)h * (NN * NN);
#pragma unroll
    for (int mf = 0; mf < 4; mf++) {
        const int row = i0 + wm + mf * 16 + g;
#pragma unroll
        for (int nf = 0; nf < 4; nf++) {
            const int col = j0 + wn + nf * 8 + 2 * c;
            float2 p0 = *(const float2*)(Pb + (size_t)row * NN + col);
            float2 p1 = *(const float2*)(Pb + (size_t)(row + 8) * NN + col);
            *(float2*)(Cb + (size_t)row * NN + col) =
                make_float2(acc[mf][nf][0] + p0.x, acc[mf][nf][1] + p0.y);
            *(float2*)(Cb + (size_t)(row + 8) * NN + col) =
                make_float2(acc[mf][nf][2] + p1.x, acc[mf][nf][3] + p1.y);
        }
    }
}

// ---------------- ctx: per-head NN GEMM, N=4096 (flattened r,d), K=512 ---------
__global__ void __launch_bounds__(256)
ctx_nn()
{
    const int h  = blockIdx.z;
    const int i0 = blockIdx.y * 128, n0 = blockIdx.x * 128;
    __shared__ float As[2][128][20];
    __shared__ float Bs[2][16][136];
    const int t = threadIdx.x, lane = t & 31, warp = t >> 5;
    const int wm = (warp >> 2) * 64, wn = (warp & 3) * 32;
    const int g = lane >> 2, c = lane & 3;
    const int ar = t >> 2, ak = 4 * (t & 3);
    const int bk = t >> 5, bn = 4 * (t & 31);

    const float* Ab = g_dots + (size_t)h * (NN * NN) + (size_t)i0 * NN;
    const float* Bb = g_vp + (size_t)h * HSZ + n0;

    auto stage = [&](int k0, int s) {
        cp16(&As[s][ar][ak],      Ab + (size_t)ar * NN + k0 + ak);
        cp16(&As[s][ar + 64][ak], Ab + (size_t)(ar + 64) * NN + k0 + ak);
        cp16(&Bs[s][bk][bn],      Bb + (size_t)(k0 + bk) * KBIG + bn);
        cp16(&Bs[s][bk + 8][bn],  Bb + (size_t)(k0 + bk + 8) * KBIG + bn);
    };

    float acc[4][4][4] = {};
    stage(0, 0); cp_commit();
    const int nit = NN / 16;   // 32
    for (int it = 0; it < nit; ++it) {
        const int s = it & 1;
        if (it + 1 < nit) { stage((it + 1) * 16, s ^ 1); cp_commit(); cp_wait<1>(); }
        else cp_wait<0>();
        __syncthreads();
#pragma unroll
        for (int ks = 0; ks < 16; ks += 8) {
            unsigned af[4][4], bf[4][2];
#pragma unroll
            for (int mf = 0; mf < 4; mf++) {
                int r0 = wm + mf * 16;
                af[mf][0] = __float_as_uint(As[s][r0 + g][ks + c]);
                af[mf][1] = __float_as_uint(As[s][r0 + g + 8][ks + c]);
                af[mf][2] = __float_as_uint(As[s][r0 + g][ks + c + 4]);
                af[mf][3] = __float_as_uint(As[s][r0 + g + 8][ks + c + 4]);
            }
#pragma unroll
            for (int nf = 0; nf < 4; nf++) {
                int n = wn + nf * 8 + g;
                bf[nf][0] = __float_as_uint(Bs[s][ks + c][n]);
                bf[nf][1] = __float_as_uint(Bs[s][ks + c + 4][n]);
            }
#pragma unroll
            for (int mf = 0; mf < 4; mf++)
#pragma unroll
                for (int nf = 0; nf < 4; nf++) mma8(acc[mf][nf], af[mf], bf[nf]);
        }
        __syncthreads();
    }

#pragma unroll
    for (int mf = 0; mf < 4; mf++) {
        const int row = i0 + wm + mf * 16 + g;
#pragma unroll
        for (int nf = 0; nf < 4; nf++) {
            const int col = n0 + wn + nf * 8 + 2 * c;
            const int r = col >> 6, d = col & 63;
            float* p = g_ctx + (size_t)r * (NN * INNERR) + h * 64 + d;
            *(float2*)(p + (size_t)row * INNERR) =
                make_float2(acc[mf][nf][0], acc[mf][nf][1]);
            *(float2*)(p + (size_t)(row + 8) * INNERR) =
                make_float2(acc[mf][nf][2], acc[mf][nf][3]);
        }
    }
}

// ---------------- soft tied row weights: w[n][h][r] (pre-scaled 0.125) --------
__global__ void rowweight_kernel()
{
    const int n = blockIdx.x, h = blockIdx.y;
    const int r = threadIdx.x;  // 64
    __shared__ float sqv[16];
    __shared__ float buf[64];
    if (r < 16) sqv[r] = g_sq[(size_t)n * DIMM + h * DSW + r];
    __syncthreads();
    const float* skp = g_sk + ((size_t)r * NN + n) * DIMM + h * DSW;
    float dot = 0.f;
#pragma unroll
    for (int d = 0; d < 16; d++) dot += sqv[d] * skp[d];
    dot *= 0.25f;
    buf[r] = dot;
    __syncthreads();
    float mx = buf[0];
#pragma unroll 8
    for (int t2 = 1; t2 < 64; t2++) mx = fmaxf(mx, buf[t2]);
    float e = expf(dot - mx);
    __syncthreads();
    buf[r] = e;
    __syncthreads();
    float s = 0.f;
#pragma unroll 8
    for (int t2 = 0; t2 < 64; t2++) s += buf[t2];
    g_w[(size_t)n * (HH * RR) + h * RR + r] = (e / s) * 0.125f;
}

// ---------------- pair bias: LN(pair[i,j,:]) @ Wpair -> g_pb[h][i][j] ---------
__global__ void pairbias_kernel(const float* __restrict__ pair,
                                const float* __restrict__ lng,
                                const float* __restrict__ lnb,
                                const float* __restrict__ Wp)
{
    const int lane = threadIdx.x & 31;
    const int warp = threadIdx.x >> 5;
    const size_t pidx = (size_t)blockIdx.x * 8 + warp;
    const float* p = pair + pidx * DPAIRR;
    float4 xv = *(const float4*)(p + lane * 4);
    float s = xv.x + xv.y + xv.z + xv.w;
#pragma unroll
    for (int o = 16; o; o >>= 1) s += __shfl_xor_sync(0xffffffffu, s, o);
    const float mu = s * (1.f / 128.f);
    float d0 = xv.x - mu, d1 = xv.y - mu, d2 = xv.z - mu, d3 = xv.w - mu;
    float vs = d0 * d0 + d1 * d1 + d2 * d2 + d3 * d3;
#pragma unroll
    for (int o = 16; o; o >>= 1) vs += __shfl_xor_sync(0xffffffffu, vs, o);
    const float inv = rsqrtf(vs * (1.f / 128.f) + 1e-5f);
    const int c = lane * 4;
    float n0 = d0 * inv * lng[c + 0] + lnb[c + 0];
    float n1 = d1 * inv * lng[c + 1] + lnb[c + 1];
    float n2 = d2 * inv * lng[c + 2] + lnb[c + 2];
    float n3 = d3 * inv * lng[c + 3] + lnb[c + 3];
    float acc[8];
#pragma unroll
    for (int h = 0; h < 8; h++)
        acc[h] = n0 * Wp[(c + 0) * 8 + h] + n1 * Wp[(c + 1) * 8 + h]
               + n2 * Wp[(c + 2) * 8 + h] + n3 * Wp[(c + 3) * 8 + h];
#pragma unroll
    for (int h = 0; h < 8; h++)
#pragma unroll
        for (int o = 16; o; o >>= 1) acc[h] += __shfl_xor_sync(0xffffffffu, acc[h], o);
    if (lane < 8)
        g_pb[(size_t)lane * (NN * NN) + pidx] = acc[lane];
}

// ---------------- softmax over j of g_dots, in-place, tf32-rounded out --------
__global__ void softmax_kernel()
{
    const int i = blockIdx.x, h = blockIdx.y;
    float* row = g_dots + ((size_t)h * NN + i) * NN;
    const int t = threadIdx.x;  // 128
    __shared__ float red[128];
    float v[4];
    float mx = -1e30f;
#pragma unroll
    for (int e = 0; e < 4; e++) { v[e] = row[t * 4 + e]; mx = fmaxf(mx, v[e]); }
    red[t] = mx; __syncthreads();
#pragma unroll
    for (int s = 64; s; s >>= 1) { if (t < s) red[t] = fmaxf(red[t], red[t + s]); __syncthreads(); }
    const float M = red[0];
    __syncthreads();
    float sum = 0.f;
#pragma unroll
    for (int e = 0; e < 4; e++) { v[e] = expf(v[e] - M); sum += v[e]; }
    red[t] = sum; __syncthreads();
#pragma unroll
    for (int s = 64; s; s >>= 1) { if (t < s) red[t] += red[t + s]; __syncthreads(); }
    const float inv = 1.f / red[0];
#pragma unroll
    for (int e = 0; e < 4; e++) row[t * 4 + e] = f2tff(v[e] * inv);
}

// ------------------------------ host ------------------------------------------
static float* symaddr(const void* s)
{
    void* p = nullptr;
    cudaGetSymbolAddress(&p, s);
    return (float*)p;
}

extern "C" void kernel_launch(void* const* d_in, const int* in_sizes, int n_in,
                              void* d_out, int out_size)
{
    const float* x     = (const float*)d_in[0];
    const float* pair  = (const float*)d_in[1];
    const float* Wq    = (const float*)d_in[2];
    const float* Wkv   = (const float*)d_in[3];
    const float* Wo    = (const float*)d_in[4];
    const float* bo    = (const float*)d_in[5];
    const float* lng   = (const float*)d_in[6];
    const float* lnb   = (const float*)d_in[7];
    const float* Wpair = (const float*)d_in[8];
    const float* Wsq   = (const float*)d_in[9];
    const float* bsq   = (const float*)d_in[10];
    const float* Wsk   = (const float*)d_in[11];
    const float* bsk   = (const float*)d_in[12];
    float* out = (float*)d_out;

    float* paq  = symaddr(g_aq);
    float* pak  = symaddr(g_ak);
    float* pvp  = symaddr(g_vp);
    float* psk  = symaddr(g_sk);
    float* psq  = symaddr(g_sq);
    float* pw   = symaddr(g_w);
    float* pctx = symaddr(g_ctx);

    dim3 blk(256);
    const int MROWS = RR * NN;   // 32768

    // sk / sq projections (needed before q, for w folding)
    gemm_nn<0><<<dim3(1, MROWS / 128), blk>>>(x, DIMM, Wsk, DIMM, bsk, psk, DIMM, nullptr, nullptr, DIMM);
    gemm_nn<0><<<dim3(1, NN / 128),    blk>>>(x, DIMM, Wsq, DIMM, bsq, psq, DIMM, nullptr, nullptr, DIMM);

    // soft tied row weights (x0.125 folded in)
    rowweight_kernel<<<dim3(NN, HH), 64>>>();

    // q projection: packed layout, w folded, tf32-rounded
    gemm_nn<2><<<dim3(INNERR / 128, MROWS / 128), blk>>>(x, DIMM, Wq, INNERR, nullptr, paq, 0, nullptr, pw, DIMM);
    // k+v projection in one pass: packed layouts, tf32-rounded
    gemm_nn<1><<<dim3((2 * INNERR) / 128, MROWS / 128), blk>>>(x, DIMM, Wkv, 2 * INNERR, nullptr, pak, 0, pvp, nullptr, DIMM);

    // pair bias (memory-bound: 134 MB read)
    pairbias_kernel<<<(NN * NN) / 8, 256>>>(pair, lng, lnb, Wpair);

    // tied attention logits (+pair bias in epilogue): per-head NT GEMM K=4096
    dots_nt<<<dim3(4, 4, HH), blk>>>();

    // softmax over j (stores tf32-rounded probs)
    softmax_kernel<<<dim3(NN, HH), 128>>>();

    // attn @ V: per-head NN GEMM N=4096
    ctx_nn<<<dim3(32, 4, HH), blk>>>();

    // output projection
    gemm_nn<0><<<dim3(1, MROWS / 128), blk>>>(pctx, INNERR, Wo, DIMM, bo, out, DIMM, nullptr, nullptr, INNERR);
}

// round 5
// speedup vs baseline: 1.9075x; 1.0507x over previous
#include <cuda_runtime.h>
#include <cstddef>
#include <cstdint>

// Problem constants
#define RR    64
#define NN    512
#define DIMM  128
#define HH    8
#define DHH   64
#define INNERR 512
#define DPAIRR 128
#define DSW   16
#define KBIG  4096
#define HSZ   ((size_t)NN * KBIG)
#define PIPE  4

// ---------------- scratch (device globals; no allocation allowed) -------------
__device__ float g_xr [(size_t)RR * NN * DIMM];   // tf32-rounded x
__device__ float g_wq [DIMM * INNERR];
__device__ float g_wkv[DIMM * 2 * INNERR];
__device__ float g_wsk[DIMM * DIMM];
__device__ float g_wsq[DIMM * DIMM];
__device__ float g_wo [INNERR * DIMM];
__device__ float g_aq [(size_t)HH * NN * KBIG];   // [h][n][r*64+d] = w*q (tf32)
__device__ float g_ak [(size_t)HH * NN * KBIG];   // k (tf32)
__device__ float g_vp [(size_t)HH * NN * KBIG];   // v (tf32)
__device__ float g_sk [(size_t)RR * NN * DIMM];
__device__ float g_sq [(size_t)NN * DIMM];
__device__ float g_w  [(size_t)NN * HH * RR];     // row weights (x0.125)
__device__ float g_dots [(size_t)HH * NN * NN];   // split-K half 0 (+pb); attn after softmax
__device__ float g_dots1[(size_t)HH * NN * NN];   // split-K half 1
__device__ float g_pb [(size_t)HH * NN * NN];
__device__ float g_ctx[(size_t)RR * NN * INNERR];

// ---------------- helpers ------------------------------------------------------
__device__ __forceinline__ unsigned f2tf(float f)
{
    unsigned u;
    asm("cvt.rna.tf32.f32 %0, %1;" : "=r"(u) : "f"(f));
    return u;
}
__device__ __forceinline__ float f2tff(float f) { return __uint_as_float(f2tf(f)); }

__device__ __forceinline__ void mma8(float* d, const unsigned* a, const unsigned* b)
{
    asm volatile(
        "mma.sync.aligned.m16n8k8.row.col.f32.tf32.tf32.f32 "
        "{%0,%1,%2,%3},{%4,%5,%6,%7},{%8,%9},{%0,%1,%2,%3};"
        : "+f"(d[0]), "+f"(d[1]), "+f"(d[2]), "+f"(d[3])
        : "r"(a[0]), "r"(a[1]), "r"(a[2]), "r"(a[3]), "r"(b[0]), "r"(b[1]));
}

__device__ __forceinline__ void cp16(void* dst, const void* src)
{
    unsigned s = (unsigned)__cvta_generic_to_shared(dst);
    asm volatile("cp.async.cg.shared.global [%0], [%1], 16;\n" :: "r"(s), "l"(src));
}
__device__ __forceinline__ void cp_commit() { asm volatile("cp.async.commit_group;\n"); }
template<int W> __device__ __forceinline__ void cp_wait()
{
    asm volatile("cp.async.wait_group %0;\n" :: "n"(W));
}

// ---------------- tf32 rounding pass ------------------------------------------
__global__ void round_tf32(const float* __restrict__ in, float* __restrict__ out, int n4)
{
    int i = blockIdx.x * blockDim.x + threadIdx.x;
    if (i < n4) {
        float4 v = ((const float4*)in)[i];
        v.x = f2tff(v.x); v.y = f2tff(v.y); v.z = f2tff(v.z); v.w = f2tff(v.w);
        ((float4*)out)[i] = v;
    }
}

// ---------------- generic NN TF32 GEMM, 4-stage cp.async, pre-rounded inputs ---
// BM=128, BN=128, BK=16, 256 thr, warp tile 64x32.
// EPI=0: C[row*ldc+col]=acc(+bias); EPI=1: packed q/k/v remap (C,C2);
// EPI=2: packed with w multiply.
#define AS(s, i, k) Asb[((s) * 128 + (i)) * 20 + (k)]
#define BS(s, i, k) Bsb[((s) * 16 + (i)) * 136 + (k)]
template<int EPI>
__global__ void __launch_bounds__(256)
gemm_nn(const float* __restrict__ A, int lda,
        const float* __restrict__ B, int ldb,
        const float* __restrict__ bias,
        float* __restrict__ C, int ldc,
        float* __restrict__ C2,
        const float* __restrict__ wtab,
        int K)
{
    extern __shared__ float smem[];
    float* Asb = smem;
    float* Bsb = smem + PIPE * 128 * 20;
    const int t = threadIdx.x, lane = t & 31, warp = t >> 5;
    const int i0 = blockIdx.y * 128, j0 = blockIdx.x * 128;
    const int wm = (warp >> 2) * 64, wn = (warp & 3) * 32;
    const int g = lane >> 2, c = lane & 3;
    const int ar = t >> 2, ak = 4 * (t & 3);
    const int bk = t >> 5, bn = 4 * (t & 31);

    const float* Ab = A + (size_t)i0 * lda;
    const float* Bb = B + j0;
    const int nit = K / 16;

    auto stage = [&](int it) {
        if (it < nit) {
            const int k0 = it * 16, s = it & (PIPE - 1);
            cp16(&AS(s, ar, ak),      Ab + (size_t)ar * lda + k0 + ak);
            cp16(&AS(s, ar + 64, ak), Ab + (size_t)(ar + 64) * lda + k0 + ak);
            cp16(&BS(s, bk, bn),      Bb + (size_t)(k0 + bk) * ldb + bn);
            cp16(&BS(s, bk + 8, bn),  Bb + (size_t)(k0 + bk + 8) * ldb + bn);
        }
        cp_commit();
    };

    float acc[4][4][4] = {};
    stage(0); stage(1); stage(2);
    for (int it = 0; it < nit; ++it) {
        const int s = it & (PIPE - 1);
        cp_wait<PIPE - 2>();
        __syncthreads();
#pragma unroll
        for (int ks = 0; ks < 16; ks += 8) {
            unsigned af[4][4], bf[4][2];
#pragma unroll
            for (int mf = 0; mf < 4; mf++) {
                int r0 = wm + mf * 16;
                af[mf][0] = __float_as_uint(AS(s, r0 + g, ks + c));
                af[mf][1] = __float_as_uint(AS(s, r0 + g + 8, ks + c));
                af[mf][2] = __float_as_uint(AS(s, r0 + g, ks + c + 4));
                af[mf][3] = __float_as_uint(AS(s, r0 + g + 8, ks + c + 4));
            }
#pragma unroll
            for (int nf = 0; nf < 4; nf++) {
                int n = wn + nf * 8 + g;
                bf[nf][0] = __float_as_uint(BS(s, ks + c, n));
                bf[nf][1] = __float_as_uint(BS(s, ks + c + 4, n));
            }
#pragma unroll
            for (int mf = 0; mf < 4; mf++)
#pragma unroll
                for (int nf = 0; nf < 4; nf++) mma8(acc[mf][nf], af[mf], bf[nf]);
        }
        stage(it + 3);
    }

#pragma unroll
    for (int mf = 0; mf < 4; mf++) {
        const int row0 = i0 + wm + mf * 16 + g;
#pragma unroll
        for (int nf = 0; nf < 4; nf++) {
            const int col = j0 + wn + nf * 8 + 2 * c;
            if (EPI == 0) {
                float b0 = bias ? bias[col] : 0.f;
                float b1 = bias ? bias[col + 1] : 0.f;
                *(float2*)(C + (size_t)row0 * ldc + col) =
                    make_float2(acc[mf][nf][0] + b0, acc[mf][nf][1] + b1);
                *(float2*)(C + (size_t)(row0 + 8) * ldc + col) =
                    make_float2(acc[mf][nf][2] + b0, acc[mf][nf][3] + b1);
            } else {
                const int ch = col >> 6, d = col & 63;
                float* base = ((EPI == 1 && ch >= 8) ? C2 : C) + (size_t)(ch & 7) * HSZ;
                const int n0r = row0 & 511, r0r = row0 >> 9;
                const int n1r = (row0 + 8) & 511, r1r = (row0 + 8) >> 9;
                float w0 = 1.f, w1 = 1.f;
                if (EPI == 2) {
                    w0 = wtab[(size_t)n0r * 512 + (ch << 6) + r0r];
                    w1 = wtab[(size_t)n1r * 512 + (ch << 6) + r1r];
                }
                *(float2*)(base + (size_t)n0r * KBIG + r0r * 64 + d) =
                    make_float2(f2tff(acc[mf][nf][0] * w0), f2tff(acc[mf][nf][1] * w0));
                *(float2*)(base + (size_t)n1r * KBIG + r1r * 64 + d) =
                    make_float2(f2tff(acc[mf][nf][2] * w1), f2tff(acc[mf][nf][3] * w1));
            }
        }
    }
}

// ---------------- dots: per-head NT GEMM, split-K 2x2048 ----------------------
#define DS(p, s, i, k) p[((s) * 128 + (i)) * 20 + (k)]
__global__ void __launch_bounds__(256)
dots_nt()
{
    const int h    = blockIdx.z & 7;
    const int half = blockIdx.z >> 3;
    const int i0 = blockIdx.y * 128, j0 = blockIdx.x * 128;
    extern __shared__ float smem[];
    float* Asb = smem;
    float* Bsb = smem + PIPE * 128 * 20;
    const int t = threadIdx.x, lane = t & 31, warp = t >> 5;
    const int wm = (warp >> 2) * 64, wn = (warp & 3) * 32;
    const int g = lane >> 2, c = lane & 3;
    const int ar = t >> 2, ak = 4 * (t & 3);

    const float* Ab = g_aq + (size_t)h * HSZ + (size_t)i0 * KBIG + half * 2048;
    const float* Bb = g_ak + (size_t)h * HSZ + (size_t)j0 * KBIG + half * 2048;
    const int nit = 2048 / 16;   // 128

    auto stage = [&](int it) {
        if (it < nit) {
            const int k0 = it * 16, s = it & (PIPE - 1);
            cp16(&DS(Asb, s, ar, ak),      Ab + (size_t)ar * KBIG + k0 + ak);
            cp16(&DS(Asb, s, ar + 64, ak), Ab + (size_t)(ar + 64) * KBIG + k0 + ak);
            cp16(&DS(Bsb, s, ar, ak),      Bb + (size_t)ar * KBIG + k0 + ak);
            cp16(&DS(Bsb, s, ar + 64, ak), Bb + (size_t)(ar + 64) * KBIG + k0 + ak);
        }
        cp_commit();
    };

    float acc[4][4][4] = {};
    stage(0); stage(1); stage(2);
    for (int it = 0; it < nit; ++it) {
        const int s = it & (PIPE - 1);
        cp_wait<PIPE - 2>();
        __syncthreads();
#pragma unroll
        for (int ks = 0; ks < 16; ks += 8) {
            unsigned af[4][4], bf[4][2];
#pragma unroll
            for (int mf = 0; mf < 4; mf++) {
                int r0 = wm + mf * 16;
                af[mf][0] = __float_as_uint(DS(Asb, s, r0 + g, ks + c));
                af[mf][1] = __float_as_uint(DS(Asb, s, r0 + g + 8, ks + c));
                af[mf][2] = __float_as_uint(DS(Asb, s, r0 + g, ks + c + 4));
                af[mf][3] = __float_as_uint(DS(Asb, s, r0 + g + 8, ks + c + 4));
            }
#pragma unroll
            for (int nf = 0; nf < 4; nf++) {
                int n = wn + nf * 8 + g;
                bf[nf][0] = __float_as_uint(DS(Bsb, s, n, ks + c));
                bf[nf][1] = __float_as_uint(DS(Bsb, s, n, ks + c + 4));
            }
#pragma unroll
            for (int mf = 0; mf < 4; mf++)
#pragma unroll
                for (int nf = 0; nf < 4; nf++) mma8(acc[mf][nf], af[mf], bf[nf]);
        }
        stage(it + 3);
    }

    float* Cb = (half ? g_dots1 : g_dots) + (size_t)h * (NN * NN);
    const float* Pb = g_pb + (size_t)h * (NN * NN);
#pragma unroll
    for (int mf = 0; mf < 4; mf++) {
        const int row = i0 + wm + mf * 16 + g;
#pragma unroll
        for (int nf = 0; nf < 4; nf++) {
            const int col = j0 + wn + nf * 8 + 2 * c;
            float2 o0 = make_float2(acc[mf][nf][0], acc[mf][nf][1]);
            float2 o1 = make_float2(acc[mf][nf][2], acc[mf][nf][3]);
            if (!half) {
                float2 p0 = *(const float2*)(Pb + (size_t)row * NN + col);
                float2 p1 = *(const float2*)(Pb + (size_t)(row + 8) * NN + col);
                o0.x += p0.x; o0.y += p0.y; o1.x += p1.x; o1.y += p1.y;
            }
            *(float2*)(Cb + (size_t)row * NN + col) = o0;
            *(float2*)(Cb + (size_t)(row + 8) * NN + col) = o1;
        }
    }
}

// ---------------- ctx: per-head NN GEMM, N=4096, K=512, 4-stage ----------------
__global__ void __launch_bounds__(256)
ctx_nn()
{
    const int h  = blockIdx.z;
    const int i0 = blockIdx.y * 128, n0 = blockIdx.x * 128;
    extern __shared__ float smem[];
    float* Asb = smem;
    float* Bsb = smem + PIPE * 128 * 20;
    const int t = threadIdx.x, lane = t & 31, warp = t >> 5;
    const int wm = (warp >> 2) * 64, wn = (warp & 3) * 32;
    const int g = lane >> 2, c = lane & 3;
    const int ar = t >> 2, ak = 4 * (t & 3);
    const int bk = t >> 5, bn = 4 * (t & 31);

    const float* Ab = g_dots + (size_t)h * (NN * NN) + (size_t)i0 * NN;
    const float* Bb = g_vp + (size_t)h * HSZ + n0;
    const int nit = NN / 16;   // 32

    auto stage = [&](int it) {
        if (it < nit) {
            const int k0 = it * 16, s = it & (PIPE - 1);
            cp16(&AS(s, ar, ak),      Ab + (size_t)ar * NN + k0 + ak);
            cp16(&AS(s, ar + 64, ak), Ab + (size_t)(ar + 64) * NN + k0 + ak);
            cp16(&BS(s, bk, bn),      Bb + (size_t)(k0 + bk) * KBIG + bn);
            cp16(&BS(s, bk + 8, bn),  Bb + (size_t)(k0 + bk + 8) * KBIG + bn);
        }
        cp_commit();
    };

    float acc[4][4][4] = {};
    stage(0); stage(1); stage(2);
    for (int it = 0; it < nit; ++it) {
        const int s = it & (PIPE - 1);
        cp_wait<PIPE - 2>();
        __syncthreads();
#pragma unroll
        for (int ks = 0; ks < 16; ks += 8) {
            unsigned af[4][4], bf[4][2];
#pragma unroll
            for (int mf = 0; mf < 4; mf++) {
                int r0 = wm + mf * 16;
                af[mf][0] = __float_as_uint(AS(s, r0 + g, ks + c));
                af[mf][1] = __float_as_uint(AS(s, r0 + g + 8, ks + c));
                af[mf][2] = __float_as_uint(AS(s, r0 + g, ks + c + 4));
                af[mf][3] = __float_as_uint(AS(s, r0 + g + 8, ks + c + 4));
            }
#pragma unroll
            for (int nf = 0; nf < 4; nf++) {
                int n = wn + nf * 8 + g;
                bf[nf][0] = __float_as_uint(BS(s, ks + c, n));
                bf[nf][1] = __float_as_uint(BS(s, ks + c + 4, n));
            }
#pragma unroll
            for (int mf = 0; mf < 4; mf++)
#pragma unroll
                for (int nf = 0; nf < 4; nf++) mma8(acc[mf][nf], af[mf], bf[nf]);
        }
        stage(it + 3);
    }

#pragma unroll
    for (int mf = 0; mf < 4; mf++) {
        const int row = i0 + wm + mf * 16 + g;
#pragma unroll
        for (int nf = 0; nf < 4; nf++) {
            const int col = n0 + wn + nf * 8 + 2 * c;
            const int r = col >> 6, d = col & 63;
            float* p = g_ctx + (size_t)r * (NN * INNERR) + h * 64 + d;
            *(float2*)(p + (size_t)row * INNERR) =
                make_float2(acc[mf][nf][0], acc[mf][nf][1]);
            *(float2*)(p + (size_t)(row + 8) * INNERR) =
                make_float2(acc[mf][nf][2], acc[mf][nf][3]);
        }
    }
}

// ---------------- soft tied row weights ---------------------------------------
__global__ void rowweight_kernel()
{
    const int n = blockIdx.x, h = blockIdx.y;
    const int r = threadIdx.x;  // 64
    __shared__ float sqv[16];
    __shared__ float buf[64];
    if (r < 16) sqv[r] = g_sq[(size_t)n * DIMM + h * DSW + r];
    __syncthreads();
    const float* skp = g_sk + ((size_t)r * NN + n) * DIMM + h * DSW;
    float dot = 0.f;
#pragma unroll
    for (int d = 0; d < 16; d++) dot += sqv[d] * skp[d];
    dot *= 0.25f;
    buf[r] = dot;
    __syncthreads();
    float mx = buf[0];
#pragma unroll 8
    for (int t2 = 1; t2 < 64; t2++) mx = fmaxf(mx, buf[t2]);
    float e = expf(dot - mx);
    __syncthreads();
    buf[r] = e;
    __syncthreads();
    float s = 0.f;
#pragma unroll 8
    for (int t2 = 0; t2 < 64; t2++) s += buf[t2];
    g_w[(size_t)n * (HH * RR) + h * RR + r] = (e / s) * 0.125f;
}

// ---------------- pair bias ----------------------------------------------------
__global__ void pairbias_kernel(const float* __restrict__ pair,
                                const float* __restrict__ lng,
                                const float* __restrict__ lnb,
                                const float* __restrict__ Wp)
{
    const int lane = threadIdx.x & 31;
    const int warp = threadIdx.x >> 5;
    const size_t pidx = (size_t)blockIdx.x * 8 + warp;
    const float* p = pair + pidx * DPAIRR;
    float4 xv = *(const float4*)(p + lane * 4);
    float s = xv.x + xv.y + xv.z + xv.w;
#pragma unroll
    for (int o = 16; o; o >>= 1) s += __shfl_xor_sync(0xffffffffu, s, o);
    const float mu = s * (1.f / 128.f);
    float d0 = xv.x - mu, d1 = xv.y - mu, d2 = xv.z - mu, d3 = xv.w - mu;
    float vs = d0 * d0 + d1 * d1 + d2 * d2 + d3 * d3;
#pragma unroll
    for (int o = 16; o; o >>= 1) vs += __shfl_xor_sync(0xffffffffu, vs, o);
    const float inv = rsqrtf(vs * (1.f / 128.f) + 1e-5f);
    const int c = lane * 4;
    float n0 = d0 * inv * lng[c + 0] + lnb[c + 0];
    float n1 = d1 * inv * lng[c + 1] + lnb[c + 1];
    float n2 = d2 * inv * lng[c + 2] + lnb[c + 2];
    float n3 = d3 * inv * lng[c + 3] + lnb[c + 3];
    float acc[8];
#pragma unroll
    for (int h = 0; h < 8; h++)
        acc[h] = n0 * Wp[(c + 0) * 8 + h] + n1 * Wp[(c + 1) * 8 + h]
               + n2 * Wp[(c + 2) * 8 + h] + n3 * Wp[(c + 3) * 8 + h];
#pragma unroll
    for (int h = 0; h < 8; h++)
#pragma unroll
        for (int o = 16; o; o >>= 1) acc[h] += __shfl_xor_sync(0xffffffffu, acc[h], o);
    if (lane < 8)
        g_pb[(size_t)lane * (NN * NN) + pidx] = acc[lane];
}

// ---------------- softmax: sum split-K halves, softmax, tf32-round -------------
__global__ void softmax_kernel()
{
    const int i = blockIdx.x, h = blockIdx.y;
    float* row  = g_dots  + ((size_t)h * NN + i) * NN;
    const float* row1 = g_dots1 + ((size_t)h * NN + i) * NN;
    const int t = threadIdx.x;  // 128
    __shared__ float red[128];
    float v[4];
    float mx = -1e30f;
#pragma unroll
    for (int e = 0; e < 4; e++) {
        v[e] = row[t * 4 + e] + row1[t * 4 + e];
        mx = fmaxf(mx, v[e]);
    }
    red[t] = mx; __syncthreads();
#pragma unroll
    for (int s = 64; s; s >>= 1) { if (t < s) red[t] = fmaxf(red[t], red[t + s]); __syncthreads(); }
    const float M = red[0];
    __syncthreads();
    float sum = 0.f;
#pragma unroll
    for (int e = 0; e < 4; e++) { v[e] = expf(v[e] - M); sum += v[e]; }
    red[t] = sum; __syncthreads();
#pragma unroll
    for (int s = 64; s; s >>= 1) { if (t < s) red[t] += red[t + s]; __syncthreads(); }
    const float inv = 1.f / red[0];
#pragma unroll
    for (int e = 0; e < 4; e++) row[t * 4 + e] = f2tff(v[e] * inv);
}

// ------------------------------ host ------------------------------------------
static float* symaddr(const void* s)
{
    void* p = nullptr;
    cudaGetSymbolAddress(&p, s);
    return (float*)p;
}

extern "C" void kernel_launch(void* const* d_in, const int* in_sizes, int n_in,
                              void* d_out, int out_size)
{
    const float* x     = (const float*)d_in[0];
    const float* pair  = (const float*)d_in[1];
    const float* Wq    = (const float*)d_in[2];
    const float* Wkv   = (const float*)d_in[3];
    const float* Wo    = (const float*)d_in[4];
    const float* bo    = (const float*)d_in[5];
    const float* lng   = (const float*)d_in[6];
    const float* lnb   = (const float*)d_in[7];
    const float* Wpair = (const float*)d_in[8];
    const float* Wsq   = (const float*)d_in[9];
    const float* bsq   = (const float*)d_in[10];
    const float* Wsk   = (const float*)d_in[11];
    const float* bsk   = (const float*)d_in[12];
    float* out = (float*)d_out;

    float* pxr  = symaddr(g_xr);
    float* pwq  = symaddr(g_wq);
    float* pwkv = symaddr(g_wkv);
    float* pwsk = symaddr(g_wsk);
    float* pwsq = symaddr(g_wsq);
    float* pwo  = symaddr(g_wo);
    float* paq  = symaddr(g_aq);
    float* pak  = symaddr(g_ak);
    float* pvp  = symaddr(g_vp);
    float* psk  = symaddr(g_sk);
    float* psq  = symaddr(g_sq);
    float* pw   = symaddr(g_w);
    float* pctx = symaddr(g_ctx);

    // dynamic smem sizes
    const int SM_GEMM = PIPE * (128 * 20 + 16 * 136) * 4;   // 75776 B
    const int SM_DOTS = PIPE * (128 * 20) * 2 * 4;          // 81920 B
    cudaFuncSetAttribute(gemm_nn<0>, cudaFuncAttributeMaxDynamicSharedMemorySize, SM_GEMM);
    cudaFuncSetAttribute(gemm_nn<1>, cudaFuncAttributeMaxDynamicSharedMemorySize, SM_GEMM);
    cudaFuncSetAttribute(gemm_nn<2>, cudaFuncAttributeMaxDynamicSharedMemorySize, SM_GEMM);
    cudaFuncSetAttribute(dots_nt,    cudaFuncAttributeMaxDynamicSharedMemorySize, SM_DOTS);
    cudaFuncSetAttribute(ctx_nn,     cudaFuncAttributeMaxDynamicSharedMemorySize, SM_GEMM);

    dim3 blk(256);
    const int MROWS = RR * NN;   // 32768

    // pre-round x and weights to tf32 (removes all CVT from GEMM mainloops)
    round_tf32<<<(MROWS * DIMM / 4 + 255) / 256, 256>>>(x, pxr, MROWS * DIMM / 4);
    round_tf32<<<(DIMM * INNERR / 4 + 255) / 256, 256>>>(Wq, pwq, DIMM * INNERR / 4);
    round_tf32<<<(DIMM * 2 * INNERR / 4 + 255) / 256, 256>>>(Wkv, pwkv, DIMM * 2 * INNERR / 4);
    round_tf32<<<(DIMM * DIMM / 4 + 255) / 256, 256>>>(Wsk, pwsk, DIMM * DIMM / 4);
    round_tf32<<<(DIMM * DIMM / 4 + 255) / 256, 256>>>(Wsq, pwsq, DIMM * DIMM / 4);
    round_tf32<<<(INNERR * DIMM / 4 + 255) / 256, 256>>>(Wo, pwo, INNERR * DIMM / 4);

    // sk / sq projections (needed before q, for w folding)
    gemm_nn<0><<<dim3(1, MROWS / 128), blk, SM_GEMM>>>(pxr, DIMM, pwsk, DIMM, bsk, psk, DIMM, nullptr, nullptr, DIMM);
    gemm_nn<0><<<dim3(1, NN / 128),    blk, SM_GEMM>>>(pxr, DIMM, pwsq, DIMM, bsq, psq, DIMM, nullptr, nullptr, DIMM);

    // soft tied row weights (x0.125 folded in)
    rowweight_kernel<<<dim3(NN, HH), 64>>>();

    // q projection: packed layout, w folded, tf32-rounded
    gemm_nn<2><<<dim3(INNERR / 128, MROWS / 128), blk, SM_GEMM>>>(pxr, DIMM, pwq, INNERR, nullptr, paq, 0, nullptr, pw, DIMM);
    // k+v projection in one pass
    gemm_nn<1><<<dim3((2 * INNERR) / 128, MROWS / 128), blk, SM_GEMM>>>(pxr, DIMM, pwkv, 2 * INNERR, nullptr, pak, 0, pvp, nullptr, DIMM);

    // pair bias (memory-bound: 134 MB read)
    pairbias_kernel<<<(NN * NN) / 8, 256>>>(pair, lng, lnb, Wpair);

    // tied attention logits, split-K 2x (half 0 adds pair bias)
    dots_nt<<<dim3(4, 4, 16), blk, SM_DOTS>>>();

    // softmax over j (sums split halves, stores tf32-rounded probs)
    softmax_kernel<<<dim3(NN, HH), 128>>>();

    // attn @ V
    ctx_nn<<<dim3(32, 4, HH), blk, SM_GEMM>>>();

    // output projection
    gemm_nn<0><<<dim3(1, MROWS / 128), blk, SM_GEMM>>>(pctx, INNERR, pwo, DIMM, bo, out, DIMM, nullptr, nullptr, INNERR);
}